// round 3
// baseline (speedup 1.0000x reference)
#include <cuda_runtime.h>

#define EPSF     1.1920928955078125e-07f
#define LOG2E    1.4426950408889634f
#define NSAMP    2000
#define NPAD     2048
#define Y0F      0.9999f
#define NROWS    65536
#define FULLMASK 0xffffffffu
#define NBLOCKS  304
#define NWARPS   (NBLOCKS * 8)

// Phase-1 fill table, natural order, packed pairs: (ax_{2j}, ax_{2j+1}, l2_{2j}, l2_{2j+1})
__device__ float4 g_tabQ[NPAD / 2];
// Natural-order per-point table for phase 2: (ax_i, l2_i)
__device__ float2 g_tabP[NPAD];
__device__ float  g_grid[NPAD];

__device__ __forceinline__ float ex2(float x) {
    float r;
    asm("ex2.approx.ftz.f32 %0, %1;" : "=f"(r) : "f"(x));
    return r;
}
__device__ __forceinline__ unsigned long long pk(float a, float b) {
    unsigned long long r;
    asm("mov.b64 %0, {%1, %2};" : "=l"(r) : "f"(a), "f"(b));
    return r;
}
__device__ __forceinline__ void upk(float& a, float& b, unsigned long long r) {
    asm("mov.b64 {%0, %1}, %2;" : "=f"(a), "=f"(b) : "l"(r));
}

__global__ void init_tables_kernel() {
    int i = blockIdx.x * blockDim.x + threadIdx.x;  // 0..2047
    if (i >= NPAD) return;
    const float step = 2.0f * Y0F / 1999.0f;
    float ax, l2, g;
    if (i < NSAMP) {
        float x = (i == NSAMP - 1) ? Y0F
                                   : __fadd_rn(__fmul_rn((float)i, step), -Y0F);
        ax = 0.5f * logf((1.0f + x) / (1.0f - x) + EPSF);
        l2 = -log2f(1.0f - x * x);   // log2(1/(1-x^2))
        g  = x;
    } else {
        ax = 0.0f; l2 = -1e30f; g = Y0F;   // exp2(-1e30) == 0: padding inert
    }
    g_tabP[i] = make_float2(ax, l2);
    g_grid[i] = g;
    float* fq = (float*)g_tabQ;
    int q = i >> 1, h = i & 1;
    fq[q * 4 + h]     = ax;   // .x / .y
    fq[q * 4 + 2 + h] = l2;   // .z / .w
}

// Persistent warps: one warp per row, each warp loops over rows with the
// 16KB grid table resident in registers (lane l owns points [64l, 64l+64)).
__global__ __launch_bounds__(256, 1) void sample_kernel(
    const float* __restrict__ mean,
    const float* __restrict__ stdv,
    const float* __restrict__ uni,
    float* __restrict__ out)
{
    const int lane = threadIdx.x & 31;
    const int warp = threadIdx.x >> 5;
    const int gw   = blockIdx.x * 8 + warp;

    // ---- One-time: load this lane's 64 points into registers (32 packed pairs) ----
    unsigned long long tA[32], tL[32];
    {
        const float4* tp = g_tabQ + lane * 32;
        #pragma unroll
        for (int j = 0; j < 32; ++j) {
            float4 v = __ldg(tp + j);
            tA[j] = pk(v.x, v.y);
            tL[j] = pk(v.z, v.w);
        }
    }

    for (int row = gw; row < NROWS; row += NWARPS) {
        const float mu = __ldg(mean + row);
        const float sg = __ldg(stdv + row) + EPSF;
        const float u  = __ldg(uni + row);
        const float k2 = (-0.5f * LOG2E) / (sg * sg);

        const unsigned long long nmu = pk(-mu, -mu);
        const unsigned long long k2p = pk(k2, k2);

        // ---- Phase 1: per-lane segment sums, packed f32x2 math ----
        float s0 = 0.0f, s1 = 0.0f;
        #pragma unroll
        for (int j = 0; j < 32; ++j) {
            unsigned long long t, tt, arg;
            asm("add.rn.f32x2 %0, %1, %2;"     : "=l"(t)   : "l"(tA[j]), "l"(nmu));
            asm("mul.rn.f32x2 %0, %1, %2;"     : "=l"(tt)  : "l"(t),     "l"(t));
            asm("fma.rn.f32x2 %0, %1, %2, %3;" : "=l"(arg) : "l"(tt),    "l"(k2p), "l"(tL[j]));
            float lo, hi;
            upk(lo, hi, arg);
            s0 += ex2(lo);
            s1 += ex2(hi);
        }
        float s = s0 + s1;

        // inclusive warp scan of lane sums
        float incl = s;
        #pragma unroll
        for (int o = 1; o < 32; o <<= 1) {
            float t = __shfl_up_sync(FULLMASK, incl, o);
            if (lane >= o) incl += t;
        }
        const float total = __shfl_sync(FULLMASK, incl, 31);
        const float excl  = incl - s;

        const float invnorm = rsqrtf(6.283185307179586f * sg * sg);
        const float denom   = __fmaf_rn(invnorm, total, EPSF);   // S_norm + EPS
        const float Traw    = u * denom / invnorm;               // threshold, raw space

        // ---- Phase 2: locate crossing segment, then exact index ----
        unsigned m = __ballot_sync(FULLMASK, incl > Traw);
        int idx;
        if (m == 0u) {
            float Snorm = invnorm * total;
            float cl = Snorm / (Snorm + EPSF);   // reference's cdf[last]
            idx = (u < cl) ? (NSAMP - 1) : 0;
        } else {
            const int L = __ffs(m) - 1;
            const float base = __shfl_sync(FULLMASK, excl, L);
            float T2 = Traw - base;
            const int base_i = L * 64;
            idx = -1;
            for (int sub = 0; sub < 64 && idx < 0; sub += 32) {
                int i = base_i + sub + lane;
                float2 q = __ldg(&g_tabP[i]);
                float t = q.x - mu;
                float p = ex2(__fmaf_rn(t * t, k2, q.y));
                float c = p;
                #pragma unroll
                for (int o = 1; o < 32; o <<= 1) {
                    float tt = __shfl_up_sync(FULLMASK, c, o);
                    if (lane >= o) c += tt;
                }
                unsigned mm = __ballot_sync(FULLMASK, c > T2);
                if (mm) {
                    idx = base_i + sub + (__ffs(mm) - 1);
                } else {
                    T2 -= __shfl_sync(FULLMASK, c, 31);
                }
            }
            if (idx < 0) idx = base_i + 63;        // fp drift: crossing at segment end
            if (idx > NSAMP - 1) idx = NSAMP - 1;
        }

        // ---- Recompute prob at final index ----
        float2 q = __ldg(&g_tabP[idx]);
        float t = q.x - mu;
        float p = ex2(__fmaf_rn(t * t, k2, q.y));
        float prob = invnorm * p / denom;

        if (lane == 0) {
            out[row]         = g_grid[idx];  // sampled_values
            out[NROWS + row] = prob;         // sampled_probs
        }
    }
}

extern "C" void kernel_launch(void* const* d_in, const int* in_sizes, int n_in,
                              void* d_out, int out_size) {
    const float* mean = (const float*)d_in[0];
    const float* stdv = (const float*)d_in[1];
    const float* uni  = (const float*)d_in[2];
    float* out = (float*)d_out;

    init_tables_kernel<<<2, 1024>>>();
    sample_kernel<<<NBLOCKS, 256>>>(mean, stdv, uni, out);
}

// round 4
// speedup vs baseline: 1.9200x; 1.9200x over previous
#include <cuda_runtime.h>

#define EPSF     1.1920928955078125e-07f
#define LOG2E    1.4426950408889634f
#define NSAMP    2000
#define NPAD     2048
#define Y0F      0.9999f
#define NROWS    65536
#define FULLMASK 0xffffffffu

#define NCH      16      // chunks per row
#define CPTS     128     // points per chunk
#define CF4      64      // float4 per chunk
#define CF4P     65      // padded (bank-conflict skew for lane-varying rewalk)

// Chunked padded table: g_tabC[c*CF4P + q] = (ax_{2i}, ax_{2i+1}, l2_{2i}, l2_{2i+1})
// for point pair i = c*64 + q (indices 2i = c*128 + 2q).
__device__ float4 g_tabC[NCH * CF4P];
__device__ float  g_grid[NPAD];

__device__ __forceinline__ float ex2(float x) {
    float r;
    asm("ex2.approx.ftz.f32 %0, %1;" : "=f"(r) : "f"(x));
    return r;
}
__device__ __forceinline__ unsigned long long pk(float a, float b) {
    unsigned long long r;
    asm("mov.b64 %0, {%1, %2};" : "=l"(r) : "f"(a), "f"(b));
    return r;
}
__device__ __forceinline__ void upk(float& a, float& b, unsigned long long r) {
    asm("mov.b64 {%0, %1}, %2;" : "=f"(a), "=f"(b) : "l"(r));
}

__global__ void init_tables_kernel() {
    int i = blockIdx.x * blockDim.x + threadIdx.x;  // 0..2047
    if (i >= NPAD) return;
    const float step = 2.0f * Y0F / 1999.0f;
    float ax, l2, g;
    if (i < NSAMP) {
        float x = (i == NSAMP - 1) ? Y0F
                                   : __fadd_rn(__fmul_rn((float)i, step), -Y0F);
        ax = 0.5f * logf((1.0f + x) / (1.0f - x) + EPSF);
        l2 = -log2f(1.0f - x * x);   // log2(1/(1-x^2))
        g  = x;
    } else {
        ax = 0.0f; l2 = -1e30f; g = Y0F;   // exp2(-1e30)==0: padding inert
    }
    g_grid[i] = g;
    int c = i >> 7, q = (i & 127) >> 1, h = i & 1;
    float* f = (float*)&g_tabC[c * CF4P + q];
    f[h]     = ax;
    f[2 + h] = l2;
}

// lane = row. Each warp handles 32 consecutive rows; table broadcast from smem.
__global__ __launch_bounds__(256) void sample_kernel(
    const float* __restrict__ mean,
    const float* __restrict__ stdv,
    const float* __restrict__ uni,
    float* __restrict__ out)
{
    __shared__ float4 tab[NCH * CF4P];     // 16640 B
    __shared__ float  chs[NCH * 256];      // 16384 B (per-thread chunk sums)

    const int tid = threadIdx.x;
    for (int i = tid; i < NCH * CF4P; i += 256) tab[i] = g_tabC[i];
    __syncthreads();

    const int row = blockIdx.x * 256 + tid;

    const float mu = __ldg(mean + row);
    const float sg = __ldg(stdv + row) + EPSF;
    const float u  = __ldg(uni + row);
    const float k2 = (-0.5f * LOG2E) / (sg * sg);
    const unsigned long long nmu = pk(-mu, -mu);
    const unsigned long long k2p = pk(k2, k2);

    // ---- Phase 1: sequential chunk sums (table via smem broadcast) ----
    float S = 0.0f;
    for (int k = 0; k < NCH; ++k) {
        const float4* cp = tab + k * CF4P;
        float s0 = 0.0f, s1 = 0.0f;
        #pragma unroll 16
        for (int j = 0; j < CF4; ++j) {
            float4 v = cp[j];  // broadcast: all lanes same address
            unsigned long long axp = pk(v.x, v.y);
            unsigned long long l2p = pk(v.z, v.w);
            unsigned long long t, tt, arg;
            asm("add.rn.f32x2 %0, %1, %2;"     : "=l"(t)   : "l"(axp), "l"(nmu));
            asm("mul.rn.f32x2 %0, %1, %2;"     : "=l"(tt)  : "l"(t),   "l"(t));
            asm("fma.rn.f32x2 %0, %1, %2, %3;" : "=l"(arg) : "l"(tt),  "l"(k2p), "l"(l2p));
            float lo, hi;
            upk(lo, hi, arg);
            s0 += ex2(lo);
            s1 += ex2(hi);
        }
        float cs = s0 + s1;
        chs[k * 256 + tid] = cs;
        S += cs;
    }

    const float invnorm = rsqrtf(6.283185307179586f * sg * sg);
    const float denom   = __fmaf_rn(invnorm, S, EPSF);   // S_norm + EPS
    const float Traw    = u * denom / invnorm;           // threshold, raw space

    // ---- Phase 2a: locate crossing chunk ----
    float cum = 0.0f, base = 0.0f;
    int kc = -1;
    #pragma unroll
    for (int k = 0; k < NCH; ++k) {
        float cs = chs[k * 256 + tid];
        float ni = cum + cs;
        if (kc < 0 && ni > Traw) { kc = k; base = cum; }
        cum = ni;
    }

    int idx;
    if (kc < 0) {
        // u >= cdf_last (reference argmax -> 0) or u within eps of 1 (-> last)
        float Snorm = invnorm * S;
        float cl = Snorm / (Snorm + EPSF);
        idx = (u < cl) ? (NSAMP - 1) : 0;
    } else {
        // ---- Phase 2b: sequential rewalk of the crossing chunk ----
        const float T2 = Traw - base;
        const float4* cp = tab + kc * CF4P;   // lane-varying; CF4P=65 skews banks
        float c = 0.0f;
        idx = -1;
        #pragma unroll 8
        for (int j = 0; j < CF4; ++j) {
            float4 v = cp[j];
            float t0 = v.x - mu;
            float p0 = ex2(__fmaf_rn(t0 * t0, k2, v.z));
            c += p0;
            if (idx < 0 && c > T2) idx = kc * CPTS + 2 * j;
            float t1 = v.y - mu;
            float p1 = ex2(__fmaf_rn(t1 * t1, k2, v.w));
            c += p1;
            if (idx < 0 && c > T2) idx = kc * CPTS + 2 * j + 1;
        }
        if (idx < 0) idx = kc * CPTS + CPTS - 1;   // fp drift at chunk boundary
        if (idx > NSAMP - 1) idx = NSAMP - 1;      // never lands in padding
    }

    // ---- Recompute prob at final index ----
    {
        int c2 = idx >> 7, q = (idx & 127) >> 1, h = idx & 1;
        float4 v = tab[c2 * CF4P + q];
        float ax = h ? v.y : v.x;
        float l2 = h ? v.w : v.z;
        float t = ax - mu;
        float p = ex2(__fmaf_rn(t * t, k2, l2));
        float prob = invnorm * p / denom;

        out[row]         = __ldg(g_grid + idx);  // sampled_values
        out[NROWS + row] = prob;                 // sampled_probs
    }
}

extern "C" void kernel_launch(void* const* d_in, const int* in_sizes, int n_in,
                              void* d_out, int out_size) {
    const float* mean = (const float*)d_in[0];
    const float* stdv = (const float*)d_in[1];
    const float* uni  = (const float*)d_in[2];
    float* out = (float*)d_out;

    init_tables_kernel<<<2, 1024>>>();
    sample_kernel<<<NROWS / 256, 256>>>(mean, stdv, uni, out);
}